// round 17
// baseline (speedup 1.0000x reference)
#include <cuda_runtime.h>
#include <cuda_fp16.h>
#include <cstdint>

#define NH 12
#define HD 64
#define NT 197
#define BB 64
#define EE 768
#define MT (BB*NT)      // 12608
#define NBH (BB*NH)     // 768
#define TROWS 30
#define GRID14 14
#define NTP 208         // padded NT for K^T global

// scratch (static device memory; allocation-free). Referenced ONLY from device
// code — never passed as kernel arguments from host (that was the 2^27 bug).
__device__ __align__(16) __half g_xh[MT*EE];
__device__ __align__(16) __half g_xl[MT*EE];
__device__ __align__(16) __half g_wh[EE*3*EE];   // [k][2304] = wq|wk|wv
__device__ __align__(16) __half g_wl[EE*3*EE];
__device__ __align__(16) __half g_ph[EE*EE];     // wproj [k][768]
__device__ __align__(16) __half g_pl[EE*EE];
__device__ __align__(16) __half g_qh[NBH*NT*HD]; // [bh][n][d]
__device__ __align__(16) __half g_ql[NBH*NT*HD];
__device__ __align__(16) __half g_vh[NBH*NT*HD];
__device__ __align__(16) __half g_vl[NBH*NT*HD];
__device__ __align__(16) __half g_kth[NBH*HD*NTP]; // [bh][d][208] transposed K
__device__ __align__(16) __half g_ktl[NBH*HD*NTP];
__device__ __align__(16) __half g_ch[MT*EE];     // ctx [row][768]
__device__ __align__(16) __half g_cl[MT*EE];

// ===========================================================================
// helpers — value-returning asm only
// ===========================================================================
__device__ __forceinline__ uint32_t smem_u32(const void* p) {
    uint32_t a;
    asm("{ .reg .u64 t; cvta.to.shared.u64 t, %1; cvt.u32.u64 %0, t; }" : "=r"(a) : "l"(p));
    return a;
}
__device__ __forceinline__ uint32_t f2h2(float lo, float hi_) {
    uint32_t r;
    asm("cvt.rn.f16x2.f32 %0, %1, %2;" : "=r"(r) : "f"(hi_), "f"(lo));
    return r;
}
__device__ __forceinline__ float rn16(float x) {
    float r;
    asm("{ .reg .f16 t; cvt.rn.f16.f32 t, %1; cvt.f32.f16 %0, t; }" : "=f"(r) : "f"(x));
    return r;
}
__device__ __forceinline__ void sth(char* p, float v) {
    unsigned short u;
    asm("{ .reg .f16 t; cvt.rn.f16.f32 t, %1; mov.b16 %0, t; }" : "=h"(u) : "f"(v));
    *(unsigned short*)p = u;
}
#define LDSM4(r0,r1,r2,r3,addr) \
    asm volatile("ldmatrix.sync.aligned.m8n8.x4.shared.b16 {%0,%1,%2,%3}, [%4];" \
                 : "=r"(r0), "=r"(r1), "=r"(r2), "=r"(r3) : "r"(addr))
#define LDSM4T(r0,r1,r2,r3,addr) \
    asm volatile("ldmatrix.sync.aligned.m8n8.x4.trans.shared.b16 {%0,%1,%2,%3}, [%4];" \
                 : "=r"(r0), "=r"(r1), "=r"(r2), "=r"(r3) : "r"(addr))
#define MMA_S(d0,d1,d2,d3, a0,a1,a2,a3, b0,b1) \
    asm volatile("mma.sync.aligned.m16n8k16.row.col.f32.f16.f16.f32 " \
                 "{%0,%1,%2,%3}, {%4,%5,%6,%7}, {%8,%9}, {%0,%1,%2,%3};" \
                 : "+f"(d0), "+f"(d1), "+f"(d2), "+f"(d3) \
                 : "r"(a0), "r"(a1), "r"(a2), "r"(a3), "r"(b0), "r"(b1))

// ===========================================================================
// prepass: fp32 -> fp16 hi/lo splits (write device globals from device code)
// ===========================================================================
#define SPLIT4(v, hdst, ldst) do { \
    uint32_t h0_ = f2h2((v).x, (v).y), h1_ = f2h2((v).z, (v).w); \
    uint32_t l0_ = f2h2((v).x - rn16((v).x), (v).y - rn16((v).y)); \
    uint32_t l1_ = f2h2((v).z - rn16((v).z), (v).w - rn16((v).w)); \
    *(uint2*)(hdst) = make_uint2(h0_, h1_); \
    *(uint2*)(ldst) = make_uint2(l0_, l1_); \
} while(0)

__global__ void split_x_k(const float* __restrict__ x) {
    size_t i = (size_t)blockIdx.x * 256 + threadIdx.x;
    if (i >= (size_t)MT * EE / 4) return;
    float4 v = *(const float4*)(x + i * 4);
    SPLIT4(v, &g_xh[i*4], &g_xl[i*4]);
}
__global__ void split_wqkv_k(const float* __restrict__ wq, const float* __restrict__ wk,
                             const float* __restrict__ wv) {
    size_t i = (size_t)blockIdx.x * 256 + threadIdx.x;
    if (i >= (size_t)EE * 576) return;
    int k = (int)(i / 576), c4 = (int)(i % 576) * 4;
    const float* src = (c4 < 768) ? (wq + (size_t)k * 768 + c4)
                     : (c4 < 1536) ? (wk + (size_t)k * 768 + c4 - 768)
                                   : (wv + (size_t)k * 768 + c4 - 1536);
    float4 v = *(const float4*)src;
    SPLIT4(v, &g_wh[(size_t)k*2304 + c4], &g_wl[(size_t)k*2304 + c4]);
}
__global__ void split_wp_k(const float* __restrict__ wp) {
    size_t i = (size_t)blockIdx.x * 256 + threadIdx.x;
    if (i >= (size_t)EE * EE / 4) return;
    float4 v = *(const float4*)(wp + i * 4);
    SPLIT4(v, &g_ph[i*4], &g_pl[i*4]);
}

// ===========================================================================
// mma.sync fp16 3-product GEMM, fp16 pre-split inputs selected INTERNALLY
// by MODE. 512 threads, 16 warps (4m x 4n of 32x32 warp tiles) for 2x the
// latency hiding vs the 256-thread version (gemm was latency-bound at 8
// warps/SM: issue 19.5%, tensor 51%).
// MODE 0: A=g_xh/l [MT][768], B=g_wh/l [768][2304]; epilogue scatters
//         q (natural), v (natural), k (transposed) as fp16 hi/lo.
// MODE 1: A=g_ch/l, B=g_ph/l [768][768]; epilogue fp32 out + bias.
// ===========================================================================
#define A_STRIDE 40
#define B_STRIDE 136
#define OFF_AL 10240
#define OFF_BH 20480
#define OFF_BL 29184
#define GEMM_STG 37888
#define GEMM_SMEM (2*GEMM_STG)

#define DECL_ACC(m,n) \
    float c##m##n##_0 = 0.f, c##m##n##_1 = 0.f, c##m##n##_2 = 0.f, c##m##n##_3 = 0.f

#define MMA3(m,n, B0,B1, C0,C1) \
    MMA_S(c##m##n##_0,c##m##n##_1,c##m##n##_2,c##m##n##_3, \
          ah##m##_0,ah##m##_1,ah##m##_2,ah##m##_3, B0,B1); \
    MMA_S(c##m##n##_0,c##m##n##_1,c##m##n##_2,c##m##n##_3, \
          ah##m##_0,ah##m##_1,ah##m##_2,ah##m##_3, C0,C1); \
    MMA_S(c##m##n##_0,c##m##n##_1,c##m##n##_2,c##m##n##_3, \
          al##m##_0,al##m##_1,al##m##_2,al##m##_3, B0,B1)

#define LDA(m, addr_) \
    LDSM4(ah##m##_0,ah##m##_1,ah##m##_2,ah##m##_3, (addr_)); \
    LDSM4(al##m##_0,al##m##_1,al##m##_2,al##m##_3, (addr_) + OFF_AL)

#define KSTEP(ks_) do { \
    uint32_t ah0_0,ah0_1,ah0_2,ah0_3, ah1_0,ah1_1,ah1_2,ah1_3; \
    uint32_t al0_0,al0_1,al0_2,al0_3, al1_0,al1_1,al1_2,al1_3; \
    uint32_t bh0_0,bh0_1,bh0_2,bh0_3, bh1_0,bh1_1,bh1_2,bh1_3; \
    uint32_t bl0_0,bl0_1,bl0_2,bl0_3, bl1_0,bl1_1,bl1_2,bl1_3; \
    uint32_t a0_ = stg + (uint32_t)((wm0 + r15) * A_STRIDE + (ks_)*16 + h16*8) * 2; \
    LDA(0, a0_); \
    LDA(1, a0_ + (uint32_t)(16 * A_STRIDE * 2)); \
    uint32_t b0_ = stg + OFF_BH + (uint32_t)(((ks_)*16 + r15) * B_STRIDE + wn0 + h16*8) * 2; \
    uint32_t b1_ = b0_ + 32; \
    LDSM4T(bh0_0,bh0_1,bh0_2,bh0_3, b0_); \
    LDSM4T(bh1_0,bh1_1,bh1_2,bh1_3, b1_); \
    LDSM4T(bl0_0,bl0_1,bl0_2,bl0_3, b0_ + (OFF_BL - OFF_BH)); \
    LDSM4T(bl1_0,bl1_1,bl1_2,bl1_3, b1_ + (OFF_BL - OFF_BH)); \
    MMA3(0,0, bh0_0,bh0_1, bl0_0,bl0_1); \
    MMA3(0,1, bh0_2,bh0_3, bl0_2,bl0_3); \
    MMA3(0,2, bh1_0,bh1_1, bl1_0,bl1_1); \
    MMA3(0,3, bh1_2,bh1_3, bl1_2,bl1_3); \
    MMA3(1,0, bh0_0,bh0_1, bl0_0,bl0_1); \
    MMA3(1,1, bh0_2,bh0_3, bl0_2,bl0_3); \
    MMA3(1,2, bh1_0,bh1_1, bl1_0,bl1_1); \
    MMA3(1,3, bh1_2,bh1_3, bl1_2,bl1_3); \
} while(0)

// fp16 loads: 512 threads -> 1 uint4/thread per buffer
#define LDGA(dsth, dstl, i_, k0_) do { \
    int row_ = (i_) >> 2, g_ = (i_) & 3; int gm_ = m0 + row_; \
    if (gm_ < MT) { \
        size_t so_ = (size_t)gm_ * EE + (k0_) + g_ * 8; \
        dsth = *(const uint4*)(Ah + so_); dstl = *(const uint4*)(Al + so_); \
    } else { dsth = make_uint4(0,0,0,0); dstl = make_uint4(0,0,0,0); } \
} while(0)
#define LDGB(dsth, dstl, i_, k0_) do { \
    int kr_ = (i_) >> 4, g_ = (i_) & 15; \
    size_t so_ = (size_t)((k0_) + kr_) * NCOLS + n0 + g_ * 8; \
    dsth = *(const uint4*)(Bh + so_); dstl = *(const uint4*)(Bl + so_); \
} while(0)
#define LDG_CHUNK(k0_) do { \
    LDGA(uah0, ual0, tid, (k0_)); \
    LDGB(ubh0, ubl0, tid, (k0_)); \
} while(0)

#define STS_A(uh, ul, i_) do { \
    int row_ = (i_) >> 2, g_ = (i_) & 3; \
    char* p_ = stgp + row_ * (A_STRIDE * 2) + g_ * 16; \
    *(uint4*)p_ = uh; *(uint4*)(p_ + OFF_AL) = ul; \
} while(0)
#define STS_B(uh, ul, i_) do { \
    int kr_ = (i_) >> 4, g_ = (i_) & 15; \
    char* p_ = stgp + OFF_BH + kr_ * (B_STRIDE * 2) + g_ * 16; \
    *(uint4*)p_ = uh; *(uint4*)(p_ + (OFF_BL - OFF_BH)) = ul; \
} while(0)

// MODE 0 scatter of one (row, col-pair): q/v natural 4B pairs, k transposed 2B
#define SCAT0(r_, col_, v0, v1) do { \
    int bb_ = (r_) / NT, nn_ = (r_) - bb_ * NT; \
    int which_ = (col_) / EE, cc_ = (col_) - which_ * EE; \
    int hh_ = cc_ >> 6, dd_ = cc_ & 63; \
    int bh_ = bb_ * NH + hh_; \
    uint32_t hi_ = f2h2((v0), (v1)); \
    uint32_t lo_ = f2h2((v0) - rn16(v0), (v1) - rn16(v1)); \
    if (which_ == 1) { \
        size_t o0_ = ((size_t)(bh_ * HD + dd_)) * NTP + nn_; \
        size_t o1_ = ((size_t)(bh_ * HD + dd_ + 1)) * NTP + nn_; \
        *(unsigned short*)((char*)g_kth + o0_*2) = (unsigned short)(hi_ & 0xFFFF); \
        *(unsigned short*)((char*)g_kth + o1_*2) = (unsigned short)(hi_ >> 16); \
        *(unsigned short*)((char*)g_ktl + o0_*2) = (unsigned short)(lo_ & 0xFFFF); \
        *(unsigned short*)((char*)g_ktl + o1_*2) = (unsigned short)(lo_ >> 16); \
    } else { \
        __half* bh_p = (which_ == 0) ? g_qh : g_vh; \
        __half* bl_p = (which_ == 0) ? g_ql : g_vl; \
        size_t o_ = (((size_t)bh_ * NT + nn_)) * HD + dd_; \
        *(uint32_t*)((char*)bh_p + o_*2) = hi_; \
        *(uint32_t*)((char*)bl_p + o_*2) = lo_; \
    } \
} while(0)

#define STORE2(r_, col_, v0, v1) do { \
    if (MODE == 1) { \
        float2 o_; o_.x = (v0) + bias[(col_)]; o_.y = (v1) + bias[(col_)+1]; \
        *(float2*)(Cout + (size_t)(r_) * EE + (col_)) = o_; \
    } else { \
        SCAT0(r_, col_, v0, v1); \
    } \
} while(0)

#define STORE_TILE(m,n) do { \
    int r_ = m0 + wm0 + (m)*16 + (lane >> 2); \
    int cb_ = n0 + wn0 + (n)*8 + (lane & 3) * 2; \
    if (r_ < MT)     STORE2(r_,     cb_, c##m##n##_0, c##m##n##_1); \
    if (r_ + 8 < MT) STORE2(r_ + 8, cb_, c##m##n##_2, c##m##n##_3); \
} while(0)

template<int MODE>
__global__ __launch_bounds__(512, 1)
void gemm_mma(const float* __restrict__ bias, float* __restrict__ Cout)
{
    constexpr int NCOLS = (MODE == 0) ? 3 * EE : EE;
    const __half* __restrict__ Ah = (MODE == 0) ? g_xh : g_ch;
    const __half* __restrict__ Al = (MODE == 0) ? g_xl : g_cl;
    const __half* __restrict__ Bh = (MODE == 0) ? g_wh : g_ph;
    const __half* __restrict__ Bl = (MODE == 0) ? g_wl : g_pl;

    extern __shared__ char smem_raw[];
    const uint32_t sb = smem_u32(smem_raw);
    const int tid = threadIdx.x;
    const int lane = tid & 31, wid = tid >> 5;
    const int m0 = blockIdx.y * 128, n0 = blockIdx.x * 128;
    const int wm0 = (wid >> 2) * 32, wn0 = (wid & 3) * 32;
    const int r15 = lane & 15, h16 = lane >> 4;

    DECL_ACC(0,0); DECL_ACC(0,1); DECL_ACC(0,2); DECL_ACC(0,3);
    DECL_ACC(1,0); DECL_ACC(1,1); DECL_ACC(1,2); DECL_ACC(1,3);

    uint4 uah0, ual0, ubh0, ubl0;
    LDG_CHUNK(0);

    const int NC = 24;
#pragma unroll 1
    for (int c = 0; c < NC; c++) {
        {
            char* stgp = smem_raw + (c & 1) * GEMM_STG;
            STS_A(uah0, ual0, tid);
            STS_B(ubh0, ubl0, tid);
        }
        __syncthreads();
        if (c + 1 < NC) LDG_CHUNK((c + 1) * 32);
        const uint32_t stg = sb + (c & 1) * GEMM_STG;
        KSTEP(0);
        KSTEP(1);
        __syncthreads();
    }

    STORE_TILE(0,0); STORE_TILE(0,1); STORE_TILE(0,2); STORE_TILE(0,3);
    STORE_TILE(1,0); STORE_TILE(1,1); STORE_TILE(1,2); STORE_TILE(1,3);
}

// ===========================================================================
// Fused attention (byte-identical to round 16 passing version)
// ===========================================================================
#define SKLD 272
#define SVLD 72
#define SQLD 72
#define SPLD 272
#define SSLD 272
#define AO_KSH 0
#define AO_KSL 34816
#define AO_VSH 69632
#define AO_VSL 108800
#define AO_QSH 147968
#define AO_QSL 152576
#define AO_PH  157184
#define AO_PL  174592
#define AO_S   192000
#define ATT_SMEM_BYTES 226816

#define LOADQ(ks) \
    LDSM4(qh##ks##_0,qh##ks##_1,qh##ks##_2,qh##ks##_3, qa_ + (ks)*32); \
    LDSM4(ql##ks##_0,ql##ks##_1,ql##ks##_2,ql##ks##_3, qa_ + (ks)*32 + (AO_QSL - AO_QSH))

#define SCORE_K(ks) do { \
    uint32_t kh0,kh1,kh2,kh3, kl0,kl1,kl2,kl3; \
    uint32_t ka_ = sb + AO_KSH + (uint32_t)(((ks)*16 + r15) * SKLD + n0 + h16*8) * 2; \
    LDSM4T(kh0,kh1,kh2,kh3, ka_); \
    LDSM4T(kl0,kl1,kl2,kl3, ka_ + (AO_KSL - AO_KSH)); \
    MMA_S(e0,e1,e2,e3, qh##ks##_0,qh##ks##_1,qh##ks##_2,qh##ks##_3, kh0,kh1); \
    MMA_S(e0,e1,e2,e3, qh##ks##_0,qh##ks##_1,qh##ks##_2,qh##ks##_3, kl0,kl1); \
    MMA_S(e0,e1,e2,e3, ql##ks##_0,ql##ks##_1,ql##ks##_2,ql##ks##_3, kh0,kh1); \
    MMA_S(f0,f1,f2,f3, qh##ks##_0,qh##ks##_1,qh##ks##_2,qh##ks##_3, kh2,kh3); \
    MMA_S(f0,f1,f2,f3, qh##ks##_0,qh##ks##_1,qh##ks##_2,qh##ks##_3, kl2,kl3); \
    MMA_S(f0,f1,f2,f3, ql##ks##_0,ql##ks##_1,ql##ks##_2,ql##ks##_3, kh2,kh3); \
} while(0)

__global__ __launch_bounds__(256, 1)
void attn_k(const float* __restrict__ rk_v, const float* __restrict__ rk_h,
            const float* __restrict__ rv_v, const float* __restrict__ rv_h)
{
    extern __shared__ char smem_raw[];
    char* smr = smem_raw;
    const uint32_t sb = smem_u32(smem_raw);
    const int bh = blockIdx.x >> 1;
    const int half = blockIdx.x & 1;
    const int tid = threadIdx.x;
    const int w = tid >> 5, lane = tid & 31;
    const int r15 = lane & 15, h16 = lane >> 4;
    const int b = bh / NH, h = bh - b*NH;

    // ---- phase 1: uint4 copies of pre-split K^T / V ----
    for (int i = tid; i < 64*25; i += 256) {
        int d = i / 25, c8 = i - d * 25;
        const uint4 vh = *(const uint4*)(g_kth + ((size_t)(bh*HD + d))*NTP + c8*8);
        const uint4 vl = *(const uint4*)(g_ktl + ((size_t)(bh*HD + d))*NTP + c8*8);
        char* p = smr + AO_KSH + (size_t)(d*SKLD + c8*8) * 2;
        *(uint4*)p = vh;
        *(uint4*)(p + (AO_KSL - AO_KSH)) = vl;
    }
    for (int i = tid; i < NT*8; i += 256) {
        int row = i >> 3, g = i & 7;
        const uint4 vh = *(const uint4*)(g_vh + ((size_t)(bh*NT + row))*HD + g*8);
        const uint4 vl = *(const uint4*)(g_vl + ((size_t)(bh*NT + row))*HD + g*8);
        char* p = smr + AO_VSH + (size_t)(row*SVLD + g*8) * 2;
        *(uint4*)p = vh;
        *(uint4*)(p + (AO_VSL - AO_VSH)) = vl;
    }
    for (int i = tid; i < (15*SVLD*2)/4; i += 256) {
        *(uint32_t*)(smr + AO_VSH + 257*SVLD*2 + i*4) = 0;
        *(uint32_t*)(smr + AO_VSL + 257*SVLD*2 + i*4) = 0;
    }
    __syncthreads();

    // ---- phase 2: rel-pos tables ----
    for (int i = tid; i < TROWS*HD; i += 256) {
        int t = i >> 6, d = i & 63;
        float v = rk_v[i], hv = rn16(v);
        size_t o = (size_t)(d*SKLD + 197 + t) * 2;
        sth(smr + AO_KSH + o, v); sth(smr + AO_KSL + o, v - hv);
        float v2 = rk_h[i], hv2 = rn16(v2);
        size_t o2 = (size_t)(d*SKLD + 227 + t) * 2;
        sth(smr + AO_KSH + o2, v2); sth(smr + AO_KSL + o2, v2 - hv2);
        float u = rv_v[i], hu = rn16(u);
        size_t p = (size_t)((197 + t)*SVLD + d) * 2;
        sth(smr + AO_VSH + p, u); sth(smr + AO_VSL + p, u - hu);
        float u2 = rv_h[i], hu2 = rn16(u2);
        size_t p2 = (size_t)((227 + t)*SVLD + d) * 2;
        sth(smr + AO_VSH + p2, u2); sth(smr + AO_VSL + p2, u2 - hu2);
    }
    __syncthreads();

    const int iBeg = half * 128;
    const int iEnd = half ? NT : 128;
    for (int i0 = iBeg; i0 < iEnd; i0 += 32) {
        for (int i = tid; i < 32*8; i += 256) {
            int r = i >> 3, g = i & 7;
            int gi = i0 + r;
            uint4 vh = make_uint4(0,0,0,0), vl = make_uint4(0,0,0,0);
            if (gi < NT) {
                vh = *(const uint4*)(g_qh + ((size_t)(bh*NT + gi))*HD + g*8);
                vl = *(const uint4*)(g_ql + ((size_t)(bh*NT + gi))*HD + g*8);
            }
            char* p = smr + AO_QSH + (size_t)(r*SQLD + g*8) * 2;
            *(uint4*)p = vh;
            *(uint4*)(p + (AO_QSL - AO_QSH)) = vl;
        }
        __syncthreads();

        {
            const int am0 = (w & 1) * 16;
            uint32_t qa_ = sb + AO_QSH + (uint32_t)((am0 + r15) * SQLD + h16*8) * 2;
            uint32_t qh0_0,qh0_1,qh0_2,qh0_3, qh1_0,qh1_1,qh1_2,qh1_3;
            uint32_t qh2_0,qh2_1,qh2_2,qh2_3, qh3_0,qh3_1,qh3_2,qh3_3;
            uint32_t ql0_0,ql0_1,ql0_2,ql0_3, ql1_0,ql1_1,ql1_2,ql1_3;
            uint32_t ql2_0,ql2_1,ql2_2,ql2_3, ql3_0,ql3_1,ql3_2,ql3_3;
            LOADQ(0); LOADQ(1); LOADQ(2); LOADQ(3);
            float* S = (float*)(smr + AO_S);
#pragma unroll 1
            for (int p = (w >> 1); p < 17; p += 4) {
                int n0 = p * 16;
                float e0=0,e1=0,e2=0,e3=0, f0=0,f1=0,f2=0,f3=0;
                SCORE_K(0); SCORE_K(1); SCORE_K(2); SCORE_K(3);
                float* sr0 = S + (am0 + (lane >> 2)) * SSLD + n0 + (lane & 3) * 2;
                *(float2*)sr0 = make_float2(e0, e1);
                *(float2*)(sr0 + 8*SSLD) = make_float2(e2, e3);
                *(float2*)(sr0 + 8) = make_float2(f0, f1);
                *(float2*)(sr0 + 8*SSLD + 8) = make_float2(f2, f3);
            }
        }
        __syncthreads();

        {
            float* S = (float*)(smr + AO_S);
            for (int rr = 0; rr < 4; rr++) {
                int r = w*4 + rr;
                int gi = i0 + r;
                if (gi >= NT) continue;
                float* srow = S + r*SSLD;
                int gvi = (gi > 0) ? (gi-1) / GRID14 : 0;
                int ghi = (gi > 0) ? (gi-1) % GRID14 : 0;

                float sv[7];
                float mx = -1e30f;
#pragma unroll
                for (int jj = 0; jj < 7; jj++) {
                    int j = lane + jj*32;
                    float s = -1e30f;
                    if (j < NT) {
                        int tv = 0, th = 0;
                        if (gi > 0 && j > 0) {
                            tv = (j-1)/GRID14 - gvi + 15;
                            th = (j-1)%GRID14 - ghi + 15;
                        }
                        s = (srow[j] + srow[197+tv] + srow[227+th]) * 0.125f;
                    }
                    sv[jj] = s;
                    mx = fmaxf(mx, s);
                }
#pragma unroll
                for (int o = 16; o > 0; o >>= 1) mx = fmaxf(mx, __shfl_xor_sync(0xFFFFFFFFu, mx, o));
                float sum = 0.f;
#pragma unroll
                for (int jj = 0; jj < 7; jj++) { float e = __expf(sv[jj]-mx); sv[jj] = e; sum += e; }
#pragma unroll
                for (int o = 16; o > 0; o >>= 1) sum += __shfl_xor_sync(0xFFFFFFFFu, sum, o);
                float inv = 1.f / sum;
#pragma unroll
                for (int jj = 0; jj < 7; jj++) {
                    int j = lane + jj*32;
                    if (j < NT) srow[j] = sv[jj]*inv;
                }
                __syncwarp();
                if (lane < TROWS) { srow[197+lane] = 0.f; srow[227+lane] = 0.f; }
                __syncwarp();
                if (gi == 0) {
                    if (lane == 0) { srow[197] = 1.f; srow[227] = 1.f; }
                } else {
                    if (lane < 14) {
                        float R = 0.f;
#pragma unroll
                        for (int c = 0; c < 14; c++) R += srow[1 + lane*14 + c];
                        srow[197 + (lane - gvi + 15)] = R;
                    } else if (lane == 14) {
                        float p0 = srow[0];
                        srow[197] = p0; srow[227] = p0;
                    } else if (lane >= 16 && lane < 30) {
                        int c = lane - 16;
                        float Cc = 0.f;
#pragma unroll
                        for (int g = 0; g < 14; g++) Cc += srow[1 + g*14 + c];
                        srow[227 + (c - ghi + 15)] = Cc;
                    }
                }
                __syncwarp();
            }
        }
        __syncthreads();

        {
            float* S = (float*)(smr + AO_S);
            for (int idx = tid; idx < 32 * SPLD; idx += 256) {
                int row = idx / SPLD, col = idx - row * SPLD;
                float v = (col < 257) ? S[row * SSLD + col] : 0.f;
                float hv = rn16(v);
                sth(smr + AO_PH + (size_t)idx * 2, v);
                sth(smr + AO_PL + (size_t)idx * 2, v - hv);
            }
        }
        __syncthreads();

        {
            const int am0 = (w & 1) * 16;
            const int n0v = (w >> 1) * 16;
            float u0=0,u1=0,u2=0,u3=0, t0=0,t1=0,t2=0,t3=0;
#pragma unroll 1
            for (int ks = 0; ks < 17; ks++) {
                uint32_t pa0,pa1,pa2,pa3, pb0,pb1,pb2,pb3;
                uint32_t vh0,vh1,vh2,vh3, vl0,vl1,vl2,vl3;
                uint32_t pa_ = sb + AO_PH + (uint32_t)((am0 + r15) * SPLD + ks*16 + h16*8) * 2;
                LDSM4(pa0,pa1,pa2,pa3, pa_);
                LDSM4(pb0,pb1,pb2,pb3, pa_ + (AO_PL - AO_PH));
                uint32_t va_ = sb + AO_VSH + (uint32_t)((ks*16 + r15) * SVLD + n0v + h16*8) * 2;
                LDSM4T(vh0,vh1,vh2,vh3, va_);
                LDSM4T(vl0,vl1,vl2,vl3, va_ + (AO_VSL - AO_VSH));
                MMA_S(u0,u1,u2,u3, pa0,pa1,pa2,pa3, vh0,vh1);
                MMA_S(u0,u1,u2,u3, pa0,pa1,pa2,pa3, vl0,vl1);
                MMA_S(u0,u1,u2,u3, pb0,pb1,pb2,pb3, vh0,vh1);
                MMA_S(t0,t1,t2,t3, pa0,pa1,pa2,pa3, vh2,vh3);
                MMA_S(t0,t1,t2,t3, pa0,pa1,pa2,pa3, vl2,vl3);
                MMA_S(t0,t1,t2,t3, pb0,pb1,pb2,pb3, vh2,vh3);
            }
            int gi0 = i0 + am0 + (lane >> 2);
            int cc = n0v + (lane & 3) * 2;
            if (gi0 < NT) {
                size_t base = ((size_t)(b*NT + gi0))*EE + h*HD;
                *(uint32_t*)((char*)g_ch + (base + cc)*2)     = f2h2(u0, u1);
                *(uint32_t*)((char*)g_cl + (base + cc)*2)     = f2h2(u0 - rn16(u0), u1 - rn16(u1));
                *(uint32_t*)((char*)g_ch + (base + cc + 8)*2) = f2h2(t0, t1);
                *(uint32_t*)((char*)g_cl + (base + cc + 8)*2) = f2h2(t0 - rn16(t0), t1 - rn16(t1));
            }
            if (gi0 + 8 < NT) {
                size_t base = ((size_t)(b*NT + gi0 + 8))*EE + h*HD;
                *(uint32_t*)((char*)g_ch + (base + cc)*2)     = f2h2(u2, u3);
                *(uint32_t*)((char*)g_cl + (base + cc)*2)     = f2h2(u2 - rn16(u2), u3 - rn16(u3));
                *(uint32_t*)((char*)g_ch + (base + cc + 8)*2) = f2h2(t2, t3);
                *(uint32_t*)((char*)g_cl + (base + cc + 8)*2) = f2h2(t2 - rn16(t2), t3 - rn16(t3));
            }
        }
        __syncthreads();
    }
}

// ---------------------------------------------------------------------------
extern "C" void kernel_launch(void* const* d_in, const int* in_sizes, int n_in,
                              void* d_out, int out_size)
{
    const float* x     = (const float*)d_in[0];
    const float* wq    = (const float*)d_in[1];
    const float* wk    = (const float*)d_in[2];
    const float* wv    = (const float*)d_in[3];
    const float* wproj = (const float*)d_in[4];
    const float* bproj = (const float*)d_in[5];
    const float* rk_v  = (const float*)d_in[6];
    const float* rk_h  = (const float*)d_in[7];
    const float* rv_v  = (const float*)d_in[8];
    const float* rv_h  = (const float*)d_in[9];
    float* out = (float*)d_out;

    cudaFuncSetAttribute(gemm_mma<0>, cudaFuncAttributeMaxDynamicSharedMemorySize, GEMM_SMEM);
    cudaFuncSetAttribute(gemm_mma<1>, cudaFuncAttributeMaxDynamicSharedMemorySize, GEMM_SMEM);
    cudaFuncSetAttribute(attn_k, cudaFuncAttributeMaxDynamicSharedMemorySize, ATT_SMEM_BYTES);

    split_x_k<<<(MT*EE/4 + 255)/256, 256>>>(x);
    split_wqkv_k<<<(EE*576 + 255)/256, 256>>>(wq, wk, wv);
    split_wp_k<<<(EE*EE/4 + 255)/256, 256>>>(wproj);

    dim3 g1(3*EE/128, (MT + 127)/128);
    gemm_mma<0><<<g1, 512, GEMM_SMEM>>>(nullptr, nullptr);

    attn_k<<<NBH*2, 256, ATT_SMEM_BYTES>>>(rk_v, rk_h, rv_v, rv_h);

    dim3 g2(EE/128, (MT + 127)/128);
    gemm_mma<1><<<g2, 512, GEMM_SMEM>>>(bproj, out);
}